// round 1
// baseline (speedup 1.0000x reference)
#include <cuda_runtime.h>
#include <math.h>

#define L_SEQ   4096
#define DMODEL  2048
#define NH      16
#define NKV     4
#define HDIM    128
#define KVDIM   (NKV*HDIM)     // 512
#define WINDOW  1024

// ---------------- scratch (device globals; no allocation allowed) ----------------
__device__ float g_q[(size_t)L_SEQ * DMODEL];        // 32 MB
__device__ float g_k[(size_t)L_SEQ * KVDIM];         // 8 MB
__device__ float g_v[(size_t)L_SEQ * KVDIM];         // 8 MB
__device__ float g_attn[(size_t)L_SEQ * DMODEL];     // 32 MB

// ======================= SGEMM: C[M,N] = A[M,K] @ B[K,N] =========================
// 128x128 block, BK=16, 8x8 per thread, 256 threads. All dims multiples of tile.
#define BM 128
#define BN 128
#define BK 16
#define TM 8
#define TN 8
#define AS_STRIDE 132   // padded to reduce store conflicts

__global__ __launch_bounds__(256) void sgemm_kernel(
    int M, int N, int K,
    const float* __restrict__ A, const float* __restrict__ B, float* __restrict__ C)
{
    __shared__ float As[BK * AS_STRIDE];   // transposed: As[k][m]
    __shared__ float Bs[BK * BN];          // Bs[k][n]

    const int tid = threadIdx.x;
    const int cRow = blockIdx.y, cCol = blockIdx.x;

    A += (size_t)cRow * BM * K;
    B += (size_t)cCol * BN;
    C += (size_t)cRow * BM * N + cCol * BN;

    const int aRow = tid >> 2;        // 0..63
    const int aCol = tid & 3;         // 0..3  (float4 along K)
    const int bRow = tid >> 5;        // 0..7
    const int bCol = tid & 31;        // 0..31 (float4 along N)

    const int tr = tid >> 4;          // 0..15
    const int tc = tid & 15;          // 0..15

    float acc[TM][TN];
#pragma unroll
    for (int i = 0; i < TM; i++)
#pragma unroll
        for (int j = 0; j < TN; j++) acc[i][j] = 0.f;

    float regM[TM], regN[TN];

    for (int k0 = 0; k0 < K; k0 += BK) {
#pragma unroll
        for (int r = 0; r < BM; r += 64) {
            float4 t = *(const float4*)(&A[(size_t)(aRow + r) * K + k0 + aCol * 4]);
            As[(aCol * 4 + 0) * AS_STRIDE + aRow + r] = t.x;
            As[(aCol * 4 + 1) * AS_STRIDE + aRow + r] = t.y;
            As[(aCol * 4 + 2) * AS_STRIDE + aRow + r] = t.z;
            As[(aCol * 4 + 3) * AS_STRIDE + aRow + r] = t.w;
        }
#pragma unroll
        for (int r = 0; r < BK; r += 8) {
            *(float4*)(&Bs[(bRow + r) * BN + bCol * 4]) =
                *(const float4*)(&B[(size_t)(k0 + bRow + r) * N + bCol * 4]);
        }
        __syncthreads();

#pragma unroll
        for (int k = 0; k < BK; k++) {
#pragma unroll
            for (int i = 0; i < TM; i += 4)
                *(float4*)&regM[i] = *(const float4*)&As[k * AS_STRIDE + tr * TM + i];
#pragma unroll
            for (int j = 0; j < TN; j += 4)
                *(float4*)&regN[j] = *(const float4*)&Bs[k * BN + tc * TN + j];
#pragma unroll
            for (int i = 0; i < TM; i++)
#pragma unroll
                for (int j = 0; j < TN; j++)
                    acc[i][j] += regM[i] * regN[j];
        }
        __syncthreads();
    }

#pragma unroll
    for (int i = 0; i < TM; i++) {
#pragma unroll
        for (int j = 0; j < TN; j += 4) {
            float4 t = make_float4(acc[i][j], acc[i][j+1], acc[i][j+2], acc[i][j+3]);
            *(float4*)(&C[(size_t)(tr * TM + i) * N + tc * TN + j]) = t;
        }
    }
}

// ================= RMSNorm (per head) + RoPE, in place =================
// grid: (L, nheads), block: 128 threads (one per head dim)
__global__ __launch_bounds__(128) void norm_rope_kernel(
    float* __restrict__ X, const float* __restrict__ scale,
    const int* __restrict__ positions, int rowstride)
{
    const int t = blockIdx.x;
    const int h = blockIdx.y;
    const int d = threadIdx.x;

    float* p = X + (size_t)t * rowstride + h * HDIM;
    float v = p[d];

    // sum of squares over 128
    float s = v * v;
#pragma unroll
    for (int off = 16; off > 0; off >>= 1)
        s += __shfl_xor_sync(0xffffffffu, s, off);

    __shared__ float ws[4];
    __shared__ float vals[HDIM];
    if ((d & 31) == 0) ws[d >> 5] = s;
    __syncthreads();
    float tot = ws[0] + ws[1] + ws[2] + ws[3];

    float nv = v * rsqrtf(tot * (1.f / HDIM) + 1e-6f) * scale[d];
    vals[d] = nv;
    __syncthreads();

    float pos = (float)positions[t];
    int j = d & 63;
    float fe = (2.f * (float)j) / (float)HDIM;
    float ts = powf(10000.f, fe);
    float ang = pos / ts;
    float sn, cs;
    sincosf(ang, &sn, &cs);

    float out;
    if (d < 64) out = vals[d] * cs - vals[d + 64] * sn;
    else        out = vals[d] * cs + vals[d - 64] * sn;
    p[d] = out;
}

// ==================== Flash attention, sliding window ====================
// grid: (L/64, H), 256 threads. Q tile 64 rows, K tile 64 keys, fp32.
#define FBQ 64
#define FBK 64
#define SS_STRIDE 68
#define MASKED_VAL (-3.0e38f)
#define M_INIT     (-1.0e30f)

// smem floats: Qt[128][64] + Kt[128][64] + Vs[64][128] + Ss[64][68] + m/l/c[64 each]
#define FLASH_SMEM_FLOATS (HDIM*FBQ + HDIM*FBK + FBK*HDIM + FBQ*SS_STRIDE + 3*FBQ)
#define FLASH_SMEM_BYTES  (FLASH_SMEM_FLOATS * 4)

__global__ __launch_bounds__(256) void flash_kernel(
    const float* __restrict__ Q, const float* __restrict__ K,
    const float* __restrict__ V, float* __restrict__ O)
{
    extern __shared__ float sm[];
    float* Qt = sm;                       // [d][i], stride 64
    float* Kt = Qt + HDIM * FBQ;          // [d][j], stride 64
    float* Vs = Kt + HDIM * FBK;          // [j][d], stride 128
    float* Ss = Vs + FBK * HDIM;          // [i][j], stride 68
    float* m_sh = Ss + FBQ * SS_STRIDE;
    float* l_sh = m_sh + FBQ;
    float* c_sh = l_sh + FBQ;

    const int tid = threadIdx.x;
    const int qt = blockIdx.x;
    const int h  = blockIdx.y;
    const int t0 = qt * FBQ;
    const int kvh = h >> 2;               // GQA: 4 q heads per kv head

    const float* Qg = Q + (size_t)t0 * DMODEL + h * HDIM;

    // load Q transposed: Qt[d][i]
#pragma unroll
    for (int it = 0; it < 8; it++) {
        int idx = tid + it * 256;          // 0..2047
        int i  = idx & 63;
        int d4 = idx >> 6;                 // 0..31
        float4 t = *(const float4*)(Qg + (size_t)i * DMODEL + d4 * 4);
        Qt[(d4 * 4 + 0) * FBQ + i] = t.x;
        Qt[(d4 * 4 + 1) * FBQ + i] = t.y;
        Qt[(d4 * 4 + 2) * FBQ + i] = t.z;
        Qt[(d4 * 4 + 3) * FBQ + i] = t.w;
    }
    if (tid < FBQ) { m_sh[tid] = M_INIT; l_sh[tid] = 0.f; }

    float o[4][8];
#pragma unroll
    for (int i = 0; i < 4; i++)
#pragma unroll
        for (int j = 0; j < 8; j++) o[i][j] = 0.f;

    const int tr = tid >> 4, tc = tid & 15;
    const int i0 = tr * 4;        // query rows for this thread
    const int j0 = tc * 4;        // key cols (S phase)
    const int d0 = tc * 8;        // head dims (PV phase)

    int lo = t0 - (WINDOW - 1); if (lo < 0) lo = 0;
    const int tile_lo = lo >> 6;
    const float sscale = 0.08838834764831845f;  // 1/sqrt(128)

    __syncthreads();

    for (int kt = tile_lo; kt <= qt; kt++) {
        const int kbase = kt * FBK;
        const float* Kg = K + (size_t)kbase * KVDIM + kvh * HDIM;
        const float* Vg = V + (size_t)kbase * KVDIM + kvh * HDIM;

        // load K transposed (lanes vary over key index -> conflict-free stores),
        // V row-major coalesced.
#pragma unroll
        for (int it = 0; it < 8; it++) {
            int idx = tid + it * 256;
            int j  = idx & 63;
            int d4 = idx >> 6;
            float4 t = *(const float4*)(Kg + (size_t)j * KVDIM + d4 * 4);
            Kt[(d4 * 4 + 0) * FBK + j] = t.x;
            Kt[(d4 * 4 + 1) * FBK + j] = t.y;
            Kt[(d4 * 4 + 2) * FBK + j] = t.z;
            Kt[(d4 * 4 + 3) * FBK + j] = t.w;
            int j2 = idx >> 5;
            int e4 = idx & 31;
            *(float4*)(Vs + j2 * HDIM + e4 * 4) =
                *(const float4*)(Vg + (size_t)j2 * KVDIM + e4 * 4);
        }
        __syncthreads();

        // S = (Q @ K^T) * scale, masked
        float acc[4][4];
#pragma unroll
        for (int a = 0; a < 4; a++)
#pragma unroll
            for (int b = 0; b < 4; b++) acc[a][b] = 0.f;

#pragma unroll 4
        for (int d = 0; d < HDIM; d++) {
            float4 rq = *(const float4*)(Qt + d * FBQ + i0);
            float4 rk = *(const float4*)(Kt + d * FBK + j0);
            float qv[4] = {rq.x, rq.y, rq.z, rq.w};
            float kv[4] = {rk.x, rk.y, rk.z, rk.w};
#pragma unroll
            for (int a = 0; a < 4; a++)
#pragma unroll
                for (int b = 0; b < 4; b++)
                    acc[a][b] += qv[a] * kv[b];
        }

#pragma unroll
        for (int a = 0; a < 4; a++) {
            int qi = t0 + i0 + a;
            float w[4];
#pragma unroll
            for (int b = 0; b < 4; b++) {
                int kj = kbase + j0 + b;
                bool valid = (kj <= qi) && (kj > qi - WINDOW);
                w[b] = valid ? acc[a][b] * sscale : MASKED_VAL;
            }
            *(float4*)(Ss + (i0 + a) * SS_STRIDE + j0) =
                make_float4(w[0], w[1], w[2], w[3]);
        }
        __syncthreads();

        // online softmax: 4 lanes per row, 16 cols each
        {
            int r = tid >> 2, g = tid & 3;
            float mo = m_sh[r], lold = l_sh[r];
            float* row = Ss + r * SS_STRIDE + g * 16;
            float lmax = MASKED_VAL;
#pragma unroll
            for (int c = 0; c < 16; c++) lmax = fmaxf(lmax, row[c]);
            lmax = fmaxf(lmax, __shfl_xor_sync(0xffffffffu, lmax, 1));
            lmax = fmaxf(lmax, __shfl_xor_sync(0xffffffffu, lmax, 2));
            float mn = fmaxf(mo, lmax);
            float sum = 0.f;
#pragma unroll
            for (int c = 0; c < 16; c++) {
                float p = __expf(row[c] - mn);
                row[c] = p;
                sum += p;
            }
            sum += __shfl_xor_sync(0xffffffffu, sum, 1);
            sum += __shfl_xor_sync(0xffffffffu, sum, 2);
            if (g == 0) {
                float cf = __expf(mo - mn);
                m_sh[r] = mn;
                l_sh[r] = lold * cf + sum;
                c_sh[r] = cf;
            }
        }
        __syncthreads();

        // O = O*c + P @ V
#pragma unroll
        for (int a = 0; a < 4; a++) {
            float cf = c_sh[i0 + a];
#pragma unroll
            for (int b = 0; b < 8; b++) o[a][b] *= cf;
        }
#pragma unroll 2
        for (int j = 0; j < FBK; j++) {
            float4 v0 = *(const float4*)(Vs + j * HDIM + d0);
            float4 v1 = *(const float4*)(Vs + j * HDIM + d0 + 4);
#pragma unroll
            for (int a = 0; a < 4; a++) {
                float p = Ss[(i0 + a) * SS_STRIDE + j];
                o[a][0] += p * v0.x; o[a][1] += p * v0.y;
                o[a][2] += p * v0.z; o[a][3] += p * v0.w;
                o[a][4] += p * v1.x; o[a][5] += p * v1.y;
                o[a][6] += p * v1.z; o[a][7] += p * v1.w;
            }
        }
        __syncthreads();
    }

    // epilogue: divide by l, write out
    float* Og = O + (size_t)t0 * DMODEL + h * HDIM;
#pragma unroll
    for (int a = 0; a < 4; a++) {
        float inv = 1.f / l_sh[i0 + a];
        float4 w0 = make_float4(o[a][0]*inv, o[a][1]*inv, o[a][2]*inv, o[a][3]*inv);
        float4 w1 = make_float4(o[a][4]*inv, o[a][5]*inv, o[a][6]*inv, o[a][7]*inv);
        *(float4*)(Og + (size_t)(i0 + a) * DMODEL + d0)     = w0;
        *(float4*)(Og + (size_t)(i0 + a) * DMODEL + d0 + 4) = w1;
    }
}

// ================================ launch ================================
extern "C" void kernel_launch(void* const* d_in, const int* in_sizes, int n_in,
                              void* d_out, int out_size)
{
    const float* x         = (const float*)d_in[0];
    const int*   positions = (const int*)  d_in[1];
    const float* Wq        = (const float*)d_in[2];
    const float* Wk        = (const float*)d_in[3];
    const float* Wv        = (const float*)d_in[4];
    const float* Wo        = (const float*)d_in[5];
    const float* q_scale   = (const float*)d_in[6];
    const float* k_scale   = (const float*)d_in[7];
    float* out = (float*)d_out;

    float *q_ptr, *k_ptr, *v_ptr, *attn_ptr;
    cudaGetSymbolAddress((void**)&q_ptr,    g_q);
    cudaGetSymbolAddress((void**)&k_ptr,    g_k);
    cudaGetSymbolAddress((void**)&v_ptr,    g_v);
    cudaGetSymbolAddress((void**)&attn_ptr, g_attn);

    cudaFuncSetAttribute(flash_kernel,
                         cudaFuncAttributeMaxDynamicSharedMemorySize,
                         FLASH_SMEM_BYTES);

    dim3 blk(256);
    // QKV projections
    sgemm_kernel<<<dim3(DMODEL / BN, L_SEQ / BM), blk>>>(L_SEQ, DMODEL, DMODEL, x, Wq, q_ptr);
    sgemm_kernel<<<dim3(KVDIM  / BN, L_SEQ / BM), blk>>>(L_SEQ, KVDIM,  DMODEL, x, Wk, k_ptr);
    sgemm_kernel<<<dim3(KVDIM  / BN, L_SEQ / BM), blk>>>(L_SEQ, KVDIM,  DMODEL, x, Wv, v_ptr);

    // RMSNorm + RoPE (q and k)
    norm_rope_kernel<<<dim3(L_SEQ, NH),  128>>>(q_ptr, q_scale, positions, DMODEL);
    norm_rope_kernel<<<dim3(L_SEQ, NKV), 128>>>(k_ptr, k_scale, positions, KVDIM);

    // sliding-window flash attention
    flash_kernel<<<dim3(L_SEQ / FBQ, NH), blk, FLASH_SMEM_BYTES>>>(q_ptr, k_ptr, v_ptr, attn_ptr);

    // output projection
    sgemm_kernel<<<dim3(DMODEL / BN, L_SEQ / BM), blk>>>(L_SEQ, DMODEL, DMODEL, attn_ptr, Wo, out);
}

// round 3
// speedup vs baseline: 1.6173x; 1.6173x over previous
#include <cuda_runtime.h>
#include <cuda_bf16.h>
#include <math.h>
#include <stdint.h>

#define L_SEQ   4096
#define DMODEL  2048
#define NH      16
#define NKV     4
#define HDIM    128
#define KVDIM   (NKV*HDIM)     // 512
#define WINDOW  1024

// ---------------- scratch (device globals; no allocation allowed) ----------------
__device__ float g_q[(size_t)L_SEQ * DMODEL];        // 32 MB
__device__ float g_k[(size_t)L_SEQ * KVDIM];         // 8 MB
__device__ float g_v[(size_t)L_SEQ * KVDIM];         // 8 MB
__device__ float g_attn[(size_t)L_SEQ * DMODEL];     // 32 MB

// =====================================================================
//  Tensor-core GEMM: C[M,N] = A[M,K] @ B[K,N], fp32 in/out.
//  Internally: split each fp32 into bf16 hi + bf16 lo, compute
//  C += Ah*Bh + Ah*Bl + Al*Bh with mma.sync.m16n8k16 (fp32 accum).
//  Accuracy ~ 1e-6 relative (lo*lo term ~2^-18 dropped).
//  128x128 block tile, BK=32, 8 warps (64x32 warp tile).
// =====================================================================
#define BM 128
#define BN 128
#define BKK 32
#define RSA 40     // bf16 row stride for A smem [m][k]  (80B rows, ldmatrix conflict-free)
#define RSB 136    // bf16 row stride for B smem [k][n]  (272B rows, conflict-free)

__device__ __forceinline__ void ldsm_x4(uint32_t &r0, uint32_t &r1, uint32_t &r2, uint32_t &r3,
                                        uint32_t addr) {
    asm volatile("ldmatrix.sync.aligned.m8n8.x4.shared.b16 {%0,%1,%2,%3}, [%4];"
                 : "=r"(r0), "=r"(r1), "=r"(r2), "=r"(r3) : "r"(addr));
}
__device__ __forceinline__ void ldsm_x4_t(uint32_t &r0, uint32_t &r1, uint32_t &r2, uint32_t &r3,
                                          uint32_t addr) {
    asm volatile("ldmatrix.sync.aligned.m8n8.x4.trans.shared.b16 {%0,%1,%2,%3}, [%4];"
                 : "=r"(r0), "=r"(r1), "=r"(r2), "=r"(r3) : "r"(addr));
}
__device__ __forceinline__ void mma16816(float *c, uint32_t a0, uint32_t a1, uint32_t a2,
                                         uint32_t a3, uint32_t b0, uint32_t b1) {
    asm volatile(
        "mma.sync.aligned.m16n8k16.row.col.f32.bf16.bf16.f32 "
        "{%0,%1,%2,%3}, {%4,%5,%6,%7}, {%8,%9}, {%0,%1,%2,%3};"
        : "+f"(c[0]), "+f"(c[1]), "+f"(c[2]), "+f"(c[3])
        : "r"(a0), "r"(a1), "r"(a2), "r"(a3), "r"(b0), "r"(b1));
}

__device__ __forceinline__ uint32_t pack_hi2(float x, float y, float &rx, float &ry) {
    __nv_bfloat162 h = __floats2bfloat162_rn(x, y);
    float2 hf = __bfloat1622float2(h);
    rx = x - hf.x; ry = y - hf.y;
    return *reinterpret_cast<uint32_t*>(&h);
}
__device__ __forceinline__ uint32_t pack2(float x, float y) {
    __nv_bfloat162 h = __floats2bfloat162_rn(x, y);
    return *reinterpret_cast<uint32_t*>(&h);
}

__global__ __launch_bounds__(256) void gemm_tc_kernel(
    int M, int N, int K,
    const float* __restrict__ A, const float* __restrict__ B, float* __restrict__ C)
{
    __shared__ __nv_bfloat16 Ah[BM * RSA];
    __shared__ __nv_bfloat16 Al[BM * RSA];
    __shared__ __nv_bfloat16 Bh[BKK * RSB];
    __shared__ __nv_bfloat16 Bl[BKK * RSB];

    const int tid  = threadIdx.x;
    const int lane = tid & 31;
    const int warp = tid >> 5;
    const int wm   = (warp & 1) * 64;     // warp m offset in block
    const int wn   = (warp >> 1) * 32;    // warp n offset in block

    const int m_blk = blockIdx.y * BM;
    const int n_blk = blockIdx.x * BN;

    const float* Ag = A + (size_t)m_blk * K;
    const float* Bg = B + n_blk;

    const uint32_t ah_s = (uint32_t)__cvta_generic_to_shared(Ah);
    const uint32_t al_s = (uint32_t)__cvta_generic_to_shared(Al);
    const uint32_t bh_s = (uint32_t)__cvta_generic_to_shared(Bh);
    const uint32_t bl_s = (uint32_t)__cvta_generic_to_shared(Bl);

    // per-thread ldmatrix source coordinates
    const int arow  = wm + (lane & 15);            // A smem row
    const int acol  = (lane >> 4) * 8;             // A smem col half
    const int brow  = lane & 15;                   // B smem k-row
    const int bcolb = wn + (lane >> 4) * 8;        // B smem n base

    float acc[4][4][4];
#pragma unroll
    for (int mt = 0; mt < 4; mt++)
#pragma unroll
        for (int nt = 0; nt < 4; nt++)
#pragma unroll
            for (int r = 0; r < 4; r++) acc[mt][nt][r] = 0.f;

    float4 pa[4], pb[4];

    // prologue: load first k-slab into registers
#pragma unroll
    for (int it = 0; it < 4; it++) {
        int idx = tid + it * 256;
        int ar = idx >> 3, ac = idx & 7;
        pa[it] = *(const float4*)(Ag + (size_t)ar * K + ac * 4);
        int br = idx >> 5, bc = idx & 31;
        pb[it] = *(const float4*)(Bg + (size_t)br * N + bc * 4);
    }

    for (int k0 = 0; k0 < K; k0 += BKK) {
        // convert + store current slab to smem (hi/lo split)
#pragma unroll
        for (int it = 0; it < 4; it++) {
            int idx = tid + it * 256;
            {
                int ar = idx >> 3, ac = idx & 7;
                int off = ar * RSA + ac * 4;
                float rx, ry, rz, rw;
                uint32_t h0 = pack_hi2(pa[it].x, pa[it].y, rx, ry);
                uint32_t h1 = pack_hi2(pa[it].z, pa[it].w, rz, rw);
                *(uint2*)(&Ah[off]) = make_uint2(h0, h1);
                *(uint2*)(&Al[off]) = make_uint2(pack2(rx, ry), pack2(rz, rw));
            }
            {
                int br = idx >> 5, bc = idx & 31;
                int off = br * RSB + bc * 4;
                float rx, ry, rz, rw;
                uint32_t h0 = pack_hi2(pb[it].x, pb[it].y, rx, ry);
                uint32_t h1 = pack_hi2(pb[it].z, pb[it].w, rz, rw);
                *(uint2*)(&Bh[off]) = make_uint2(h0, h1);
                *(uint2*)(&Bl[off]) = make_uint2(pack2(rx, ry), pack2(rz, rw));
            }
        }
        __syncthreads();

        // prefetch next slab (overlaps with MMA below)
        if (k0 + BKK < K) {
#pragma unroll
            for (int it = 0; it < 4; it++) {
                int idx = tid + it * 256;
                int ar = idx >> 3, ac = idx & 7;
                pa[it] = *(const float4*)(Ag + (size_t)ar * K + (k0 + BKK) + ac * 4);
                int br = idx >> 5, bc = idx & 31;
                pb[it] = *(const float4*)(Bg + (size_t)(k0 + BKK + br) * N + bc * 4);
            }
        }

#pragma unroll
        for (int kk = 0; kk < BKK; kk += 16) {
            uint32_t afh[4][4], afl[4][4], bfh[4][2], bfl[4][2];
#pragma unroll
            for (int mt = 0; mt < 4; mt++) {
                uint32_t aoff = (uint32_t)((arow + mt * 16) * RSA + kk + acol) * 2;
                ldsm_x4(afh[mt][0], afh[mt][1], afh[mt][2], afh[mt][3], ah_s + aoff);
                ldsm_x4(afl[mt][0], afl[mt][1], afl[mt][2], afl[mt][3], al_s + aoff);
            }
#pragma unroll
            for (int p = 0; p < 2; p++) {
                uint32_t boff = (uint32_t)((kk + brow) * RSB + bcolb + p * 16) * 2;
                uint32_t r0, r1, r2, r3;
                ldsm_x4_t(r0, r1, r2, r3, bh_s + boff);
                bfh[2*p][0] = r0; bfh[2*p][1] = r1; bfh[2*p+1][0] = r2; bfh[2*p+1][1] = r3;
                ldsm_x4_t(r0, r1, r2, r3, bl_s + boff);
                bfl[2*p][0] = r0; bfl[2*p][1] = r1; bfl[2*p+1][0] = r2; bfl[2*p+1][1] = r3;
            }
#pragma unroll
            for (int mt = 0; mt < 4; mt++) {
#pragma unroll
                for (int nt = 0; nt < 4; nt++) {
                    mma16816(acc[mt][nt], afh[mt][0], afh[mt][1], afh[mt][2], afh[mt][3],
                             bfh[nt][0], bfh[nt][1]);
                    mma16816(acc[mt][nt], afh[mt][0], afh[mt][1], afh[mt][2], afh[mt][3],
                             bfl[nt][0], bfl[nt][1]);
                    mma16816(acc[mt][nt], afl[mt][0], afl[mt][1], afl[mt][2], afl[mt][3],
                             bfh[nt][0], bfh[nt][1]);
                }
            }
        }
        __syncthreads();
    }

    // epilogue
#pragma unroll
    for (int mt = 0; mt < 4; mt++) {
#pragma unroll
        for (int nt = 0; nt < 4; nt++) {
            int row = m_blk + wm + mt * 16 + (lane >> 2);
            int col = n_blk + wn + nt * 8 + (lane & 3) * 2;
            *(float2*)(C + (size_t)row * N + col) =
                make_float2(acc[mt][nt][0], acc[mt][nt][1]);
            *(float2*)(C + (size_t)(row + 8) * N + col) =
                make_float2(acc[mt][nt][2], acc[mt][nt][3]);
        }
    }
}

// ================= RMSNorm (per head) + RoPE, in place =================
__global__ __launch_bounds__(128) void norm_rope_kernel(
    float* __restrict__ X, const float* __restrict__ scale,
    const int* __restrict__ positions, int rowstride)
{
    const int t = blockIdx.x;
    const int h = blockIdx.y;
    const int d = threadIdx.x;

    float* p = X + (size_t)t * rowstride + h * HDIM;
    float v = p[d];

    float s = v * v;
#pragma unroll
    for (int off = 16; off > 0; off >>= 1)
        s += __shfl_xor_sync(0xffffffffu, s, off);

    __shared__ float ws[4];
    __shared__ float vals[HDIM];
    if ((d & 31) == 0) ws[d >> 5] = s;
    __syncthreads();
    float tot = ws[0] + ws[1] + ws[2] + ws[3];

    float nv = v * rsqrtf(tot * (1.f / HDIM) + 1e-6f) * scale[d];
    vals[d] = nv;
    __syncthreads();

    float pos = (float)positions[t];
    int j = d & 63;
    float fe = (2.f * (float)j) / (float)HDIM;
    // base^fe = exp2(fe * log2(10000));  inv timescale = exp2(-fe*log2(base))
    float inv_ts = exp2f(-fe * 13.287712379549449f);
    float ang = pos * inv_ts;
    float sn, cs;
    sincosf(ang, &sn, &cs);

    float out;
    if (d < 64) out = vals[d] * cs - vals[d + 64] * sn;
    else        out = vals[d] * cs + vals[d - 64] * sn;
    p[d] = out;
}

// ==================== Flash attention, sliding window ====================
#define FBQ 64
#define FBK 64
#define SS_STRIDE 68
#define MASKED_VAL (-3.0e38f)
#define M_INIT     (-1.0e30f)

#define FLASH_SMEM_FLOATS (HDIM*FBQ + HDIM*FBK + FBK*HDIM + FBQ*SS_STRIDE + 3*FBQ)
#define FLASH_SMEM_BYTES  (FLASH_SMEM_FLOATS * 4)

__global__ __launch_bounds__(256) void flash_kernel(
    const float* __restrict__ Q, const float* __restrict__ K,
    const float* __restrict__ V, float* __restrict__ O)
{
    extern __shared__ float sm[];
    float* Qt = sm;                       // [d][i], stride 64
    float* Kt = Qt + HDIM * FBQ;          // [d][j], stride 64
    float* Vs = Kt + HDIM * FBK;          // [j][d], stride 128
    float* Ss = Vs + FBK * HDIM;          // [i][j], stride 68
    float* m_sh = Ss + FBQ * SS_STRIDE;
    float* l_sh = m_sh + FBQ;
    float* c_sh = l_sh + FBQ;

    const int tid = threadIdx.x;
    const int qt = blockIdx.x;
    const int h  = blockIdx.y;
    const int t0 = qt * FBQ;
    const int kvh = h >> 2;

    const float* Qg = Q + (size_t)t0 * DMODEL + h * HDIM;

#pragma unroll
    for (int it = 0; it < 8; it++) {
        int idx = tid + it * 256;
        int i  = idx & 63;
        int d4 = idx >> 6;
        float4 t = *(const float4*)(Qg + (size_t)i * DMODEL + d4 * 4);
        Qt[(d4 * 4 + 0) * FBQ + i] = t.x;
        Qt[(d4 * 4 + 1) * FBQ + i] = t.y;
        Qt[(d4 * 4 + 2) * FBQ + i] = t.z;
        Qt[(d4 * 4 + 3) * FBQ + i] = t.w;
    }
    if (tid < FBQ) { m_sh[tid] = M_INIT; l_sh[tid] = 0.f; }

    float o[4][8];
#pragma unroll
    for (int i = 0; i < 4; i++)
#pragma unroll
        for (int j = 0; j < 8; j++) o[i][j] = 0.f;

    const int tr = tid >> 4, tc = tid & 15;
    const int i0 = tr * 4;
    const int j0 = tc * 4;
    const int d0 = tc * 8;

    int lo = t0 - (WINDOW - 1); if (lo < 0) lo = 0;
    const int tile_lo = lo >> 6;
    const float sscale = 0.08838834764831845f;

    __syncthreads();

    for (int kt = tile_lo; kt <= qt; kt++) {
        const int kbase = kt * FBK;
        const float* Kg = K + (size_t)kbase * KVDIM + kvh * HDIM;
        const float* Vg = V + (size_t)kbase * KVDIM + kvh * HDIM;

#pragma unroll
        for (int it = 0; it < 8; it++) {
            int idx = tid + it * 256;
            int j  = idx & 63;
            int d4 = idx >> 6;
            float4 t = *(const float4*)(Kg + (size_t)j * KVDIM + d4 * 4);
            Kt[(d4 * 4 + 0) * FBK + j] = t.x;
            Kt[(d4 * 4 + 1) * FBK + j] = t.y;
            Kt[(d4 * 4 + 2) * FBK + j] = t.z;
            Kt[(d4 * 4 + 3) * FBK + j] = t.w;
            int j2 = idx >> 5;
            int e4 = idx & 31;
            *(float4*)(Vs + j2 * HDIM + e4 * 4) =
                *(const float4*)(Vg + (size_t)j2 * KVDIM + e4 * 4);
        }
        __syncthreads();

        float acc[4][4];
#pragma unroll
        for (int a = 0; a < 4; a++)
#pragma unroll
            for (int b = 0; b < 4; b++) acc[a][b] = 0.f;

#pragma unroll 4
        for (int d = 0; d < HDIM; d++) {
            float4 rq = *(const float4*)(Qt + d * FBQ + i0);
            float4 rk = *(const float4*)(Kt + d * FBK + j0);
            float qv[4] = {rq.x, rq.y, rq.z, rq.w};
            float kv[4] = {rk.x, rk.y, rk.z, rk.w};
#pragma unroll
            for (int a = 0; a < 4; a++)
#pragma unroll
                for (int b = 0; b < 4; b++)
                    acc[a][b] += qv[a] * kv[b];
        }

#pragma unroll
        for (int a = 0; a < 4; a++) {
            int qi = t0 + i0 + a;
            float w[4];
#pragma unroll
            for (int b = 0; b < 4; b++) {
                int kj = kbase + j0 + b;
                bool valid = (kj <= qi) && (kj > qi - WINDOW);
                w[b] = valid ? acc[a][b] * sscale : MASKED_VAL;
            }
            *(float4*)(Ss + (i0 + a) * SS_STRIDE + j0) =
                make_float4(w[0], w[1], w[2], w[3]);
        }
        __syncthreads();

        {
            int r = tid >> 2, g = tid & 3;
            float mo = m_sh[r], lold = l_sh[r];
            float* row = Ss + r * SS_STRIDE + g * 16;
            float lmax = MASKED_VAL;
#pragma unroll
            for (int c = 0; c < 16; c++) lmax = fmaxf(lmax, row[c]);
            lmax = fmaxf(lmax, __shfl_xor_sync(0xffffffffu, lmax, 1));
            lmax = fmaxf(lmax, __shfl_xor_sync(0xffffffffu, lmax, 2));
            float mn = fmaxf(mo, lmax);
            float sum = 0.f;
#pragma unroll
            for (int c = 0; c < 16; c++) {
                float p = __expf(row[c] - mn);
                row[c] = p;
                sum += p;
            }
            sum += __shfl_xor_sync(0xffffffffu, sum, 1);
            sum += __shfl_xor_sync(0xffffffffu, sum, 2);
            if (g == 0) {
                float cf = __expf(mo - mn);
                m_sh[r] = mn;
                l_sh[r] = lold * cf + sum;
                c_sh[r] = cf;
            }
        }
        __syncthreads();

#pragma unroll
        for (int a = 0; a < 4; a++) {
            float cf = c_sh[i0 + a];
#pragma unroll
            for (int b = 0; b < 8; b++) o[a][b] *= cf;
        }
#pragma unroll 2
        for (int j = 0; j < FBK; j++) {
            float4 v0 = *(const float4*)(Vs + j * HDIM + d0);
            float4 v1 = *(const float4*)(Vs + j * HDIM + d0 + 4);
#pragma unroll
            for (int a = 0; a < 4; a++) {
                float p = Ss[(i0 + a) * SS_STRIDE + j];
                o[a][0] += p * v0.x; o[a][1] += p * v0.y;
                o[a][2] += p * v0.z; o[a][3] += p * v0.w;
                o[a][4] += p * v1.x; o[a][5] += p * v1.y;
                o[a][6] += p * v1.z; o[a][7] += p * v1.w;
            }
        }
        __syncthreads();
    }

    float* Og = O + (size_t)t0 * DMODEL + h * HDIM;
#pragma unroll
    for (int a = 0; a < 4; a++) {
        float inv = 1.f / l_sh[i0 + a];
        float4 w0 = make_float4(o[a][0]*inv, o[a][1]*inv, o[a][2]*inv, o[a][3]*inv);
        float4 w1 = make_float4(o[a][4]*inv, o[a][5]*inv, o[a][6]*inv, o[a][7]*inv);
        *(float4*)(Og + (size_t)(i0 + a) * DMODEL + d0)     = w0;
        *(float4*)(Og + (size_t)(i0 + a) * DMODEL + d0 + 4) = w1;
    }
}

// ================================ launch ================================
extern "C" void kernel_launch(void* const* d_in, const int* in_sizes, int n_in,
                              void* d_out, int out_size)
{
    const float* x         = (const float*)d_in[0];
    const int*   positions = (const int*)  d_in[1];
    const float* Wq        = (const float*)d_in[2];
    const float* Wk        = (const float*)d_in[3];
    const float* Wv        = (const float*)d_in[4];
    const float* Wo        = (const float*)d_in[5];
    const float* q_scale   = (const float*)d_in[6];
    const float* k_scale   = (const float*)d_in[7];
    float* out = (float*)d_out;

    float *q_ptr, *k_ptr, *v_ptr, *attn_ptr;
    cudaGetSymbolAddress((void**)&q_ptr,    g_q);
    cudaGetSymbolAddress((void**)&k_ptr,    g_k);
    cudaGetSymbolAddress((void**)&v_ptr,    g_v);
    cudaGetSymbolAddress((void**)&attn_ptr, g_attn);

    cudaFuncSetAttribute(flash_kernel,
                         cudaFuncAttributeMaxDynamicSharedMemorySize,
                         FLASH_SMEM_BYTES);

    dim3 blk(256);
    // QKV projections (tensor cores, bf16-split)
    gemm_tc_kernel<<<dim3(DMODEL / BN, L_SEQ / BM), blk>>>(L_SEQ, DMODEL, DMODEL, x, Wq, q_ptr);
    gemm_tc_kernel<<<dim3(KVDIM  / BN, L_SEQ / BM), blk>>>(L_SEQ, KVDIM,  DMODEL, x, Wk, k_ptr);
    gemm_tc_kernel<<<dim3(KVDIM  / BN, L_SEQ / BM), blk>>>(L_SEQ, KVDIM,  DMODEL, x, Wv, v_ptr);

    // RMSNorm + RoPE (q and k)
    norm_rope_kernel<<<dim3(L_SEQ, NH),  128>>>(q_ptr, q_scale, positions, DMODEL);
    norm_rope_kernel<<<dim3(L_SEQ, NKV), 128>>>(k_ptr, k_scale, positions, KVDIM);

    // sliding-window flash attention (fp32 SIMT — next optimization target)
    flash_kernel<<<dim3(L_SEQ / FBQ, NH), blk, FLASH_SMEM_BYTES>>>(q_ptr, k_ptr, v_ptr, attn_ptr);

    // output projection (tensor cores)
    gemm_tc_kernel<<<dim3(DMODEL / BN, L_SEQ / BM), blk>>>(L_SEQ, DMODEL, DMODEL, attn_ptr, Wo, out);
}

// round 4
// speedup vs baseline: 2.6286x; 1.6252x over previous
#include <cuda_runtime.h>
#include <cuda_bf16.h>
#include <math.h>
#include <stdint.h>

#define L_SEQ   4096
#define DMODEL  2048
#define NH      16
#define NKV     4
#define HDIM    128
#define KVDIM   (NKV*HDIM)     // 512
#define WINDOW  1024

// ---------------- scratch (device globals; no allocation allowed) ----------------
__device__ float g_q[(size_t)L_SEQ * DMODEL];        // 32 MB
__device__ float g_k[(size_t)L_SEQ * KVDIM];         // 8 MB
__device__ float g_v[(size_t)L_SEQ * KVDIM];         // 8 MB
__device__ float g_attn[(size_t)L_SEQ * DMODEL];     // 32 MB

// ============================ common MMA helpers ============================
__device__ __forceinline__ void ldsm_x4(uint32_t &r0, uint32_t &r1, uint32_t &r2, uint32_t &r3,
                                        uint32_t addr) {
    asm volatile("ldmatrix.sync.aligned.m8n8.x4.shared.b16 {%0,%1,%2,%3}, [%4];"
                 : "=r"(r0), "=r"(r1), "=r"(r2), "=r"(r3) : "r"(addr));
}
__device__ __forceinline__ void ldsm_x4_t(uint32_t &r0, uint32_t &r1, uint32_t &r2, uint32_t &r3,
                                          uint32_t addr) {
    asm volatile("ldmatrix.sync.aligned.m8n8.x4.trans.shared.b16 {%0,%1,%2,%3}, [%4];"
                 : "=r"(r0), "=r"(r1), "=r"(r2), "=r"(r3) : "r"(addr));
}
__device__ __forceinline__ void mma16816(float *c, uint32_t a0, uint32_t a1, uint32_t a2,
                                         uint32_t a3, uint32_t b0, uint32_t b1) {
    asm volatile(
        "mma.sync.aligned.m16n8k16.row.col.f32.bf16.bf16.f32 "
        "{%0,%1,%2,%3}, {%4,%5,%6,%7}, {%8,%9}, {%0,%1,%2,%3};"
        : "+f"(c[0]), "+f"(c[1]), "+f"(c[2]), "+f"(c[3])
        : "r"(a0), "r"(a1), "r"(a2), "r"(a3), "r"(b0), "r"(b1));
}
__device__ __forceinline__ uint32_t pack_hi2(float x, float y, float &rx, float &ry) {
    __nv_bfloat162 h = __floats2bfloat162_rn(x, y);
    float2 hf = __bfloat1622float2(h);
    rx = x - hf.x; ry = y - hf.y;
    return *reinterpret_cast<uint32_t*>(&h);
}
__device__ __forceinline__ uint32_t pack2(float x, float y) {
    __nv_bfloat162 h = __floats2bfloat162_rn(x, y);
    return *reinterpret_cast<uint32_t*>(&h);
}

// =====================================================================
//  Tensor-core GEMM (bf16 hi/lo split), 128x128 tile, BK=32, 8 warps.
// =====================================================================
#define BM 128
#define BN 128
#define BKK 32
#define RSA 40
#define RSB 136

__global__ __launch_bounds__(256) void gemm_tc_kernel(
    int M, int N, int K,
    const float* __restrict__ A, const float* __restrict__ B, float* __restrict__ C)
{
    __shared__ __nv_bfloat16 Ah[BM * RSA];
    __shared__ __nv_bfloat16 Al[BM * RSA];
    __shared__ __nv_bfloat16 Bh[BKK * RSB];
    __shared__ __nv_bfloat16 Bl[BKK * RSB];

    const int tid  = threadIdx.x;
    const int lane = tid & 31;
    const int warp = tid >> 5;
    const int wm   = (warp & 1) * 64;
    const int wn   = (warp >> 1) * 32;

    const int m_blk = blockIdx.y * BM;
    const int n_blk = blockIdx.x * BN;

    const float* Ag = A + (size_t)m_blk * K;
    const float* Bg = B + n_blk;

    const uint32_t ah_s = (uint32_t)__cvta_generic_to_shared(Ah);
    const uint32_t al_s = (uint32_t)__cvta_generic_to_shared(Al);
    const uint32_t bh_s = (uint32_t)__cvta_generic_to_shared(Bh);
    const uint32_t bl_s = (uint32_t)__cvta_generic_to_shared(Bl);

    const int arow  = wm + (lane & 15);
    const int acol  = (lane >> 4) * 8;
    const int brow  = lane & 15;
    const int bcolb = wn + (lane >> 4) * 8;

    float acc[4][4][4];
#pragma unroll
    for (int mt = 0; mt < 4; mt++)
#pragma unroll
        for (int nt = 0; nt < 4; nt++)
#pragma unroll
            for (int r = 0; r < 4; r++) acc[mt][nt][r] = 0.f;

    float4 pa[4], pb[4];

#pragma unroll
    for (int it = 0; it < 4; it++) {
        int idx = tid + it * 256;
        int ar = idx >> 3, ac = idx & 7;
        pa[it] = *(const float4*)(Ag + (size_t)ar * K + ac * 4);
        int br = idx >> 5, bc = idx & 31;
        pb[it] = *(const float4*)(Bg + (size_t)br * N + bc * 4);
    }

    for (int k0 = 0; k0 < K; k0 += BKK) {
#pragma unroll
        for (int it = 0; it < 4; it++) {
            int idx = tid + it * 256;
            {
                int ar = idx >> 3, ac = idx & 7;
                int off = ar * RSA + ac * 4;
                float rx, ry, rz, rw;
                uint32_t h0 = pack_hi2(pa[it].x, pa[it].y, rx, ry);
                uint32_t h1 = pack_hi2(pa[it].z, pa[it].w, rz, rw);
                *(uint2*)(&Ah[off]) = make_uint2(h0, h1);
                *(uint2*)(&Al[off]) = make_uint2(pack2(rx, ry), pack2(rz, rw));
            }
            {
                int br = idx >> 5, bc = idx & 31;
                int off = br * RSB + bc * 4;
                float rx, ry, rz, rw;
                uint32_t h0 = pack_hi2(pb[it].x, pb[it].y, rx, ry);
                uint32_t h1 = pack_hi2(pb[it].z, pb[it].w, rz, rw);
                *(uint2*)(&Bh[off]) = make_uint2(h0, h1);
                *(uint2*)(&Bl[off]) = make_uint2(pack2(rx, ry), pack2(rz, rw));
            }
        }
        __syncthreads();

        if (k0 + BKK < K) {
#pragma unroll
            for (int it = 0; it < 4; it++) {
                int idx = tid + it * 256;
                int ar = idx >> 3, ac = idx & 7;
                pa[it] = *(const float4*)(Ag + (size_t)ar * K + (k0 + BKK) + ac * 4);
                int br = idx >> 5, bc = idx & 31;
                pb[it] = *(const float4*)(Bg + (size_t)(k0 + BKK + br) * N + bc * 4);
            }
        }

#pragma unroll
        for (int kk = 0; kk < BKK; kk += 16) {
            uint32_t afh[4][4], afl[4][4], bfh[4][2], bfl[4][2];
#pragma unroll
            for (int mt = 0; mt < 4; mt++) {
                uint32_t aoff = (uint32_t)((arow + mt * 16) * RSA + kk + acol) * 2;
                ldsm_x4(afh[mt][0], afh[mt][1], afh[mt][2], afh[mt][3], ah_s + aoff);
                ldsm_x4(afl[mt][0], afl[mt][1], afl[mt][2], afl[mt][3], al_s + aoff);
            }
#pragma unroll
            for (int p = 0; p < 2; p++) {
                uint32_t boff = (uint32_t)((kk + brow) * RSB + bcolb + p * 16) * 2;
                uint32_t r0, r1, r2, r3;
                ldsm_x4_t(r0, r1, r2, r3, bh_s + boff);
                bfh[2*p][0] = r0; bfh[2*p][1] = r1; bfh[2*p+1][0] = r2; bfh[2*p+1][1] = r3;
                ldsm_x4_t(r0, r1, r2, r3, bl_s + boff);
                bfl[2*p][0] = r0; bfl[2*p][1] = r1; bfl[2*p+1][0] = r2; bfl[2*p+1][1] = r3;
            }
#pragma unroll
            for (int mt = 0; mt < 4; mt++) {
#pragma unroll
                for (int nt = 0; nt < 4; nt++) {
                    mma16816(acc[mt][nt], afh[mt][0], afh[mt][1], afh[mt][2], afh[mt][3],
                             bfh[nt][0], bfh[nt][1]);
                    mma16816(acc[mt][nt], afh[mt][0], afh[mt][1], afh[mt][2], afh[mt][3],
                             bfl[nt][0], bfl[nt][1]);
                    mma16816(acc[mt][nt], afl[mt][0], afl[mt][1], afl[mt][2], afl[mt][3],
                             bfh[nt][0], bfh[nt][1]);
                }
            }
        }
        __syncthreads();
    }

#pragma unroll
    for (int mt = 0; mt < 4; mt++) {
#pragma unroll
        for (int nt = 0; nt < 4; nt++) {
            int row = m_blk + wm + mt * 16 + (lane >> 2);
            int col = n_blk + wn + nt * 8 + (lane & 3) * 2;
            *(float2*)(C + (size_t)row * N + col) =
                make_float2(acc[mt][nt][0], acc[mt][nt][1]);
            *(float2*)(C + (size_t)(row + 8) * N + col) =
                make_float2(acc[mt][nt][2], acc[mt][nt][3]);
        }
    }
}

// ================= RMSNorm (per head) + RoPE, in place =================
__global__ __launch_bounds__(128) void norm_rope_kernel(
    float* __restrict__ X, const float* __restrict__ scale,
    const int* __restrict__ positions, int rowstride)
{
    const int t = blockIdx.x;
    const int h = blockIdx.y;
    const int d = threadIdx.x;

    float* p = X + (size_t)t * rowstride + h * HDIM;
    float v = p[d];

    float s = v * v;
#pragma unroll
    for (int off = 16; off > 0; off >>= 1)
        s += __shfl_xor_sync(0xffffffffu, s, off);

    __shared__ float ws[4];
    __shared__ float vals[HDIM];
    if ((d & 31) == 0) ws[d >> 5] = s;
    __syncthreads();
    float tot = ws[0] + ws[1] + ws[2] + ws[3];

    float nv = v * rsqrtf(tot * (1.f / HDIM) + 1e-6f) * scale[d];
    vals[d] = nv;
    __syncthreads();

    float pos = (float)positions[t];
    int j = d & 63;
    float fe = (2.f * (float)j) / (float)HDIM;
    float inv_ts = exp2f(-fe * 13.287712379549449f);
    float ang = pos * inv_ts;
    float sn, cs;
    sincosf(ang, &sn, &cs);

    float out;
    if (d < 64) out = vals[d] * cs - vals[d + 64] * sn;
    else        out = vals[d] * cs + vals[d - 64] * sn;
    p[d] = out;
}

// ==================== Tensor-core flash attention (bf16 split) ====================
// q-tile 64 (4 warps x 16 rows), key tile 64. Q/K/V in smem as bf16 hi+lo.
// S = QhKh+QhKl+QlKh; softmax in registers; O += PhVh+PlVh+PhVl.
#define FQT 64
#define FKT 64
#define RSQ 136   // Q smem [row][d] stride (bf16)
#define RSK 72    // K^T smem [d][key] stride
#define RSV 136   // V smem [key][d] stride

#define QH_OFF 0
#define QL_OFF 8704
#define KH_OFF 17408
#define KL_OFF 26624
#define VH_OFF 35840
#define VL_OFF 44544
#define FLASH_SMEM_ELEMS 53248
#define FLASH_SMEM_BYTES (FLASH_SMEM_ELEMS * 2)

__global__ __launch_bounds__(128) void flash_tc_kernel(
    const float* __restrict__ Q, const float* __restrict__ K,
    const float* __restrict__ V, float* __restrict__ O)
{
    extern __shared__ __nv_bfloat16 sm[];
    const int tid  = threadIdx.x;
    const int lane = tid & 31;
    const int warp = tid >> 5;
    const int qb   = blockIdx.x;
    const int h    = blockIdx.y;
    const int t0   = qb * FQT;
    const int kvh  = h >> 2;

    const uint32_t smb  = (uint32_t)__cvta_generic_to_shared(sm);
    const uint32_t qh_s = smb + QH_OFF * 2;
    const uint32_t ql_s = smb + QL_OFF * 2;
    const uint32_t kh_s = smb + KH_OFF * 2;
    const uint32_t kl_s = smb + KL_OFF * 2;
    const uint32_t vh_s = smb + VH_OFF * 2;
    const uint32_t vl_s = smb + VL_OFF * 2;

    // ---- stage Q (hi/lo) into smem ----
    const float* Qg = Q + (size_t)t0 * DMODEL + h * HDIM;
#pragma unroll
    for (int it = 0; it < 16; it++) {
        int idx = tid + it * 128;
        int i = idx >> 5, d4 = idx & 31;
        float4 t = *(const float4*)(Qg + (size_t)i * DMODEL + d4 * 4);
        float rx, ry, rz, rw;
        uint32_t h0 = pack_hi2(t.x, t.y, rx, ry);
        uint32_t h1 = pack_hi2(t.z, t.w, rz, rw);
        *(uint2*)(&sm[QH_OFF + i * RSQ + d4 * 4]) = make_uint2(h0, h1);
        *(uint2*)(&sm[QL_OFF + i * RSQ + d4 * 4]) = make_uint2(pack2(rx, ry), pack2(rz, rw));
    }
    __syncthreads();

    // fragment coordinates (identical patterns to gemm_tc_kernel)
    const int arow  = warp * 16 + (lane & 15);
    const int acol8 = (lane >> 4) * 8;
    const int brow  = lane & 15;
    const int bcol8 = (lane >> 4) * 8;
    const int r  = lane >> 2;
    const int c2 = (lane & 3) * 2;
    const int row0 = t0 + warp * 16 + r;
    const int row1 = row0 + 8;

    float o[16][4];
#pragma unroll
    for (int nt = 0; nt < 16; nt++)
#pragma unroll
        for (int q = 0; q < 4; q++) o[nt][q] = 0.f;

    float m0 = -1e20f, m1 = -1e20f, l0 = 0.f, l1 = 0.f;

    int lo = t0 - (WINDOW - 1); if (lo < 0) lo = 0;
    const int tlo = lo >> 6;
    const int thi = qb;   // (t0+63)>>6
    const float sscale = 0.08838834764831845f;

    for (int kt = tlo; kt <= thi; kt++) {
        const int kbase = kt * FKT;
        const float* Kg = K + (size_t)kbase * KVDIM + kvh * HDIM;
        const float* Vg = V + (size_t)kbase * KVDIM + kvh * HDIM;

        // ---- load K (transposed, [d][key]) and V ([key][d]) as hi/lo ----
#pragma unroll
        for (int it = 0; it < 16; it++) {
            int idx = tid + it * 128;
            {   // K transpose-scatter
                int j = idx & 63, d4 = idx >> 6;
                float4 t = *(const float4*)(Kg + (size_t)j * KVDIM + d4 * 4);
                float e[4] = {t.x, t.y, t.z, t.w};
#pragma unroll
                for (int ee = 0; ee < 4; ee++) {
                    __nv_bfloat16 hv = __float2bfloat16_rn(e[ee]);
                    float res = e[ee] - __bfloat162float(hv);
                    sm[KH_OFF + (d4 * 4 + ee) * RSK + j] = hv;
                    sm[KL_OFF + (d4 * 4 + ee) * RSK + j] = __float2bfloat16_rn(res);
                }
            }
            {   // V direct
                int j = idx >> 5, d4 = idx & 31;
                float4 t = *(const float4*)(Vg + (size_t)j * KVDIM + d4 * 4);
                float rx, ry, rz, rw;
                uint32_t h0 = pack_hi2(t.x, t.y, rx, ry);
                uint32_t h1 = pack_hi2(t.z, t.w, rz, rw);
                *(uint2*)(&sm[VH_OFF + j * RSV + d4 * 4]) = make_uint2(h0, h1);
                *(uint2*)(&sm[VL_OFF + j * RSV + d4 * 4]) = make_uint2(pack2(rx, ry), pack2(rz, rw));
            }
        }
        __syncthreads();

        // ---- S = Q K^T (bf16 split, 3 MMAs) ----
        float s[8][4];
#pragma unroll
        for (int nt = 0; nt < 8; nt++)
#pragma unroll
            for (int q = 0; q < 4; q++) s[nt][q] = 0.f;

#pragma unroll
        for (int ks = 0; ks < 8; ks++) {
            uint32_t qah0, qah1, qah2, qah3, qal0, qal1, qal2, qal3;
            uint32_t qoff = (uint32_t)(arow * RSQ + ks * 16 + acol8) * 2;
            ldsm_x4(qah0, qah1, qah2, qah3, qh_s + qoff);
            ldsm_x4(qal0, qal1, qal2, qal3, ql_s + qoff);
#pragma unroll
            for (int p = 0; p < 4; p++) {
                uint32_t boff = (uint32_t)((ks * 16 + brow) * RSK + p * 16 + bcol8) * 2;
                uint32_t kh0, kh1, kh2, kh3, kl0, kl1, kl2, kl3;
                ldsm_x4_t(kh0, kh1, kh2, kh3, kh_s + boff);
                ldsm_x4_t(kl0, kl1, kl2, kl3, kl_s + boff);
                mma16816(s[2*p],   qah0, qah1, qah2, qah3, kh0, kh1);
                mma16816(s[2*p],   qah0, qah1, qah2, qah3, kl0, kl1);
                mma16816(s[2*p],   qal0, qal1, qal2, qal3, kh0, kh1);
                mma16816(s[2*p+1], qah0, qah1, qah2, qah3, kh2, kh3);
                mma16816(s[2*p+1], qah0, qah1, qah2, qah3, kl2, kl3);
                mma16816(s[2*p+1], qal0, qal1, qal2, qal3, kh2, kh3);
            }
        }

        // ---- mask + scale + online softmax (registers) ----
        float rm0 = -1e30f, rm1 = -1e30f;
#pragma unroll
        for (int nt = 0; nt < 8; nt++) {
            int kj = kbase + nt * 8 + c2;
#pragma unroll
            for (int e = 0; e < 2; e++) {
                int kc = kj + e;
                bool v0 = (kc <= row0) && (kc >= row0 - (WINDOW - 1));
                bool v1 = (kc <= row1) && (kc >= row1 - (WINDOW - 1));
                s[nt][e]     = v0 ? s[nt][e]     * sscale : -1e30f;
                s[nt][2 + e] = v1 ? s[nt][2 + e] * sscale : -1e30f;
                rm0 = fmaxf(rm0, s[nt][e]);
                rm1 = fmaxf(rm1, s[nt][2 + e]);
            }
        }
        rm0 = fmaxf(rm0, __shfl_xor_sync(0xffffffffu, rm0, 1));
        rm0 = fmaxf(rm0, __shfl_xor_sync(0xffffffffu, rm0, 2));
        rm1 = fmaxf(rm1, __shfl_xor_sync(0xffffffffu, rm1, 1));
        rm1 = fmaxf(rm1, __shfl_xor_sync(0xffffffffu, rm1, 2));

        float mn0 = fmaxf(m0, rm0);
        float mn1 = fmaxf(m1, rm1);
        float cf0 = __expf(m0 - mn0);
        float cf1 = __expf(m1 - mn1);
        float sum0 = 0.f, sum1 = 0.f;
#pragma unroll
        for (int nt = 0; nt < 8; nt++) {
            s[nt][0] = __expf(s[nt][0] - mn0);
            s[nt][1] = __expf(s[nt][1] - mn0);
            s[nt][2] = __expf(s[nt][2] - mn1);
            s[nt][3] = __expf(s[nt][3] - mn1);
            sum0 += s[nt][0] + s[nt][1];
            sum1 += s[nt][2] + s[nt][3];
        }
        sum0 += __shfl_xor_sync(0xffffffffu, sum0, 1);
        sum0 += __shfl_xor_sync(0xffffffffu, sum0, 2);
        sum1 += __shfl_xor_sync(0xffffffffu, sum1, 1);
        sum1 += __shfl_xor_sync(0xffffffffu, sum1, 2);

        m0 = mn0; m1 = mn1;
        l0 = l0 * cf0 + sum0;
        l1 = l1 * cf1 + sum1;
#pragma unroll
        for (int nt = 0; nt < 16; nt++) {
            o[nt][0] *= cf0; o[nt][1] *= cf0;
            o[nt][2] *= cf1; o[nt][3] *= cf1;
        }

        // ---- build P fragments (hi/lo) from S accumulators ----
        uint32_t pfh[4][4], pfl[4][4];
#pragma unroll
        for (int kk = 0; kk < 4; kk++) {
            int ta = 2 * kk, tb = 2 * kk + 1;
            float la, lb;
            pfh[kk][0] = pack_hi2(s[ta][0], s[ta][1], la, lb); pfl[kk][0] = pack2(la, lb);
            pfh[kk][1] = pack_hi2(s[ta][2], s[ta][3], la, lb); pfl[kk][1] = pack2(la, lb);
            pfh[kk][2] = pack_hi2(s[tb][0], s[tb][1], la, lb); pfl[kk][2] = pack2(la, lb);
            pfh[kk][3] = pack_hi2(s[tb][2], s[tb][3], la, lb); pfl[kk][3] = pack2(la, lb);
        }

        // ---- O += P V (bf16 split, 3 MMAs) ----
#pragma unroll
        for (int kk = 0; kk < 4; kk++) {
#pragma unroll
            for (int p = 0; p < 8; p++) {
                uint32_t boff = (uint32_t)((kk * 16 + brow) * RSV + p * 16 + bcol8) * 2;
                uint32_t vh0, vh1, vh2, vh3, vl0, vl1, vl2, vl3;
                ldsm_x4_t(vh0, vh1, vh2, vh3, vh_s + boff);
                ldsm_x4_t(vl0, vl1, vl2, vl3, vl_s + boff);
                mma16816(o[2*p],   pfh[kk][0], pfh[kk][1], pfh[kk][2], pfh[kk][3], vh0, vh1);
                mma16816(o[2*p],   pfl[kk][0], pfl[kk][1], pfl[kk][2], pfl[kk][3], vh0, vh1);
                mma16816(o[2*p],   pfh[kk][0], pfh[kk][1], pfh[kk][2], pfh[kk][3], vl0, vl1);
                mma16816(o[2*p+1], pfh[kk][0], pfh[kk][1], pfh[kk][2], pfh[kk][3], vh2, vh3);
                mma16816(o[2*p+1], pfl[kk][0], pfl[kk][1], pfl[kk][2], pfl[kk][3], vh2, vh3);
                mma16816(o[2*p+1], pfh[kk][0], pfh[kk][1], pfh[kk][2], pfh[kk][3], vl2, vl3);
            }
        }
        __syncthreads();
    }

    // ---- epilogue: divide by l, write ----
    float inv0 = 1.f / l0;
    float inv1 = 1.f / l1;
    float* Og = O + (size_t)0 * DMODEL + h * HDIM;
#pragma unroll
    for (int nt = 0; nt < 16; nt++) {
        int col = nt * 8 + c2;
        *(float2*)(Og + (size_t)row0 * DMODEL + col) =
            make_float2(o[nt][0] * inv0, o[nt][1] * inv0);
        *(float2*)(Og + (size_t)row1 * DMODEL + col) =
            make_float2(o[nt][2] * inv1, o[nt][3] * inv1);
    }
}

// ================================ launch ================================
extern "C" void kernel_launch(void* const* d_in, const int* in_sizes, int n_in,
                              void* d_out, int out_size)
{
    const float* x         = (const float*)d_in[0];
    const int*   positions = (const int*)  d_in[1];
    const float* Wq        = (const float*)d_in[2];
    const float* Wk        = (const float*)d_in[3];
    const float* Wv        = (const float*)d_in[4];
    const float* Wo        = (const float*)d_in[5];
    const float* q_scale   = (const float*)d_in[6];
    const float* k_scale   = (const float*)d_in[7];
    float* out = (float*)d_out;

    float *q_ptr, *k_ptr, *v_ptr, *attn_ptr;
    cudaGetSymbolAddress((void**)&q_ptr,    g_q);
    cudaGetSymbolAddress((void**)&k_ptr,    g_k);
    cudaGetSymbolAddress((void**)&v_ptr,    g_v);
    cudaGetSymbolAddress((void**)&attn_ptr, g_attn);

    cudaFuncSetAttribute(flash_tc_kernel,
                         cudaFuncAttributeMaxDynamicSharedMemorySize,
                         FLASH_SMEM_BYTES);

    dim3 blk(256);
    // QKV projections (tensor cores, bf16-split)
    gemm_tc_kernel<<<dim3(DMODEL / BN, L_SEQ / BM), blk>>>(L_SEQ, DMODEL, DMODEL, x, Wq, q_ptr);
    gemm_tc_kernel<<<dim3(KVDIM  / BN, L_SEQ / BM), blk>>>(L_SEQ, KVDIM,  DMODEL, x, Wk, k_ptr);
    gemm_tc_kernel<<<dim3(KVDIM  / BN, L_SEQ / BM), blk>>>(L_SEQ, KVDIM,  DMODEL, x, Wv, v_ptr);

    // RMSNorm + RoPE (q and k)
    norm_rope_kernel<<<dim3(L_SEQ, NH),  128>>>(q_ptr, q_scale, positions, DMODEL);
    norm_rope_kernel<<<dim3(L_SEQ, NKV), 128>>>(k_ptr, k_scale, positions, KVDIM);

    // sliding-window flash attention (tensor cores, bf16-split)
    flash_tc_kernel<<<dim3(L_SEQ / FQT, NH), 128, FLASH_SMEM_BYTES>>>(q_ptr, k_ptr, v_ptr, attn_ptr);

    // output projection (tensor cores)
    gemm_tc_kernel<<<dim3(DMODEL / BN, L_SEQ / BM), blk>>>(L_SEQ, DMODEL, DMODEL, attn_ptr, Wo, out);
}

// round 5
// speedup vs baseline: 2.8127x; 1.0700x over previous
#include <cuda_runtime.h>
#include <cuda_bf16.h>
#include <math.h>
#include <stdint.h>

#define L_SEQ   4096
#define DMODEL  2048
#define NH      16
#define NKV     4
#define HDIM    128
#define KVDIM   (NKV*HDIM)     // 512
#define WINDOW  1024

// ---------------- scratch (device globals; no allocation allowed) ----------------
__device__ float g_q[(size_t)L_SEQ * DMODEL];        // fp32 q (pre-norm)
__device__ float g_k[(size_t)L_SEQ * KVDIM];
__device__ float g_v[(size_t)L_SEQ * KVDIM];

// bf16 hi/lo split operands
__device__ __nv_bfloat16 g_xh[(size_t)L_SEQ * DMODEL];
__device__ __nv_bfloat16 g_xl[(size_t)L_SEQ * DMODEL];
__device__ __nv_bfloat16 g_wqh[(size_t)DMODEL * DMODEL];
__device__ __nv_bfloat16 g_wql[(size_t)DMODEL * DMODEL];
__device__ __nv_bfloat16 g_wkh[(size_t)DMODEL * KVDIM];
__device__ __nv_bfloat16 g_wkl[(size_t)DMODEL * KVDIM];
__device__ __nv_bfloat16 g_wvh[(size_t)DMODEL * KVDIM];
__device__ __nv_bfloat16 g_wvl[(size_t)DMODEL * KVDIM];
__device__ __nv_bfloat16 g_woh[(size_t)DMODEL * DMODEL];
__device__ __nv_bfloat16 g_wol[(size_t)DMODEL * DMODEL];
__device__ __nv_bfloat16 g_qh[(size_t)L_SEQ * DMODEL];
__device__ __nv_bfloat16 g_ql[(size_t)L_SEQ * DMODEL];
__device__ __nv_bfloat16 g_kh[(size_t)L_SEQ * KVDIM];
__device__ __nv_bfloat16 g_kl[(size_t)L_SEQ * KVDIM];
__device__ __nv_bfloat16 g_vh[(size_t)L_SEQ * KVDIM];
__device__ __nv_bfloat16 g_vl[(size_t)L_SEQ * KVDIM];
__device__ __nv_bfloat16 g_ah[(size_t)L_SEQ * DMODEL];   // attention output hi
__device__ __nv_bfloat16 g_al[(size_t)L_SEQ * DMODEL];   // attention output lo

// ============================ common helpers ============================
__device__ __forceinline__ void ldsm_x4(uint32_t &r0, uint32_t &r1, uint32_t &r2, uint32_t &r3,
                                        uint32_t addr) {
    asm volatile("ldmatrix.sync.aligned.m8n8.x4.shared.b16 {%0,%1,%2,%3}, [%4];"
                 : "=r"(r0), "=r"(r1), "=r"(r2), "=r"(r3) : "r"(addr));
}
__device__ __forceinline__ void ldsm_x4_t(uint32_t &r0, uint32_t &r1, uint32_t &r2, uint32_t &r3,
                                          uint32_t addr) {
    asm volatile("ldmatrix.sync.aligned.m8n8.x4.trans.shared.b16 {%0,%1,%2,%3}, [%4];"
                 : "=r"(r0), "=r"(r1), "=r"(r2), "=r"(r3) : "r"(addr));
}
__device__ __forceinline__ void mma16816(float *c, uint32_t a0, uint32_t a1, uint32_t a2,
                                         uint32_t a3, uint32_t b0, uint32_t b1) {
    asm volatile(
        "mma.sync.aligned.m16n8k16.row.col.f32.bf16.bf16.f32 "
        "{%0,%1,%2,%3}, {%4,%5,%6,%7}, {%8,%9}, {%0,%1,%2,%3};"
        : "+f"(c[0]), "+f"(c[1]), "+f"(c[2]), "+f"(c[3])
        : "r"(a0), "r"(a1), "r"(a2), "r"(a3), "r"(b0), "r"(b1));
}
__device__ __forceinline__ uint32_t pack_hi2(float x, float y, float &rx, float &ry) {
    __nv_bfloat162 h = __floats2bfloat162_rn(x, y);
    float2 hf = __bfloat1622float2(h);
    rx = x - hf.x; ry = y - hf.y;
    return *reinterpret_cast<uint32_t*>(&h);
}
__device__ __forceinline__ uint32_t pack2(float x, float y) {
    __nv_bfloat162 h = __floats2bfloat162_rn(x, y);
    return *reinterpret_cast<uint32_t*>(&h);
}
__device__ __forceinline__ void cp16(uint32_t dst, const void* src) {
    asm volatile("cp.async.cg.shared.global [%0], [%1], 16;\n" :: "r"(dst), "l"(src));
}
#define CP_COMMIT() asm volatile("cp.async.commit_group;\n" ::: "memory")
#define CP_WAIT(n)  asm volatile("cp.async.wait_group %0;\n" :: "n"(n) : "memory")

// ============ split: fp32 -> bf16 hi/lo (vectorized, memory-bound) ============
__global__ __launch_bounds__(256) void split_kernel(
    const float4* __restrict__ src, uint2* __restrict__ dh, uint2* __restrict__ dl, int n4)
{
    int i = blockIdx.x * blockDim.x + threadIdx.x;
    if (i < n4) {
        float4 t = src[i];
        float rx, ry, rz, rw;
        uint32_t h0 = pack_hi2(t.x, t.y, rx, ry);
        uint32_t h1 = pack_hi2(t.z, t.w, rz, rw);
        dh[i] = make_uint2(h0, h1);
        dl[i] = make_uint2(pack2(rx, ry), pack2(rz, rw));
    }
}

// =====================================================================
//  Tensor-core GEMM on pre-split bf16 hi/lo operands.
//  C[M,N] += Ah*Bh + Ah*Bl + Al*Bh.  128x128 tile, BK=32, 8 warps,
//  cp.async double-buffered smem.
// =====================================================================
#define BM 128
#define BN 128
#define BKK 32
#define RSA 40
#define RSB 136
#define ASZ (BM * RSA)     // 5120 elems per A buffer
#define BSZ (BKK * RSB)    // 4352 elems per B buffer
// smem elems: AH[2] AL[2] BH[2] BL[2]
#define GO_AH 0
#define GO_AL (2 * ASZ)
#define GO_BH (4 * ASZ)
#define GO_BL (4 * ASZ + 2 * BSZ)
#define GEMM_SMEM_ELEMS (4 * ASZ + 4 * BSZ)
#define GEMM_SMEM_BYTES (GEMM_SMEM_ELEMS * 2)

__global__ __launch_bounds__(256) void gemm_tc2_kernel(
    int M, int N, int K,
    const __nv_bfloat16* __restrict__ Agh, const __nv_bfloat16* __restrict__ Agl,
    const __nv_bfloat16* __restrict__ Bgh, const __nv_bfloat16* __restrict__ Bgl,
    float* __restrict__ C)
{
    extern __shared__ __nv_bfloat16 smg[];
    const int tid  = threadIdx.x;
    const int lane = tid & 31;
    const int warp = tid >> 5;
    const int wm   = (warp & 1) * 64;
    const int wn   = (warp >> 1) * 32;

    const int m_blk = blockIdx.y * BM;
    const int n_blk = blockIdx.x * BN;

    Agh += (size_t)m_blk * K;  Agl += (size_t)m_blk * K;
    Bgh += n_blk;              Bgl += n_blk;

    const uint32_t smb  = (uint32_t)__cvta_generic_to_shared(smg);
    const uint32_t ah_s = smb + GO_AH * 2;
    const uint32_t al_s = smb + GO_AL * 2;
    const uint32_t bh_s = smb + GO_BH * 2;
    const uint32_t bl_s = smb + GO_BL * 2;

    const int arow  = wm + (lane & 15);
    const int acol  = (lane >> 4) * 8;
    const int brow  = lane & 15;
    const int bcolb = wn + (lane >> 4) * 8;

    float acc[4][4][4];
#pragma unroll
    for (int mt = 0; mt < 4; mt++)
#pragma unroll
        for (int nt = 0; nt < 4; nt++)
#pragma unroll
            for (int r = 0; r < 4; r++) acc[mt][nt][r] = 0.f;

    // per-thread cp.async coordinates
    // A: 512 chunks of 8 elems; idx = tid + it*256
    // B: 512 chunks of 8 elems
    auto load_stage = [&](int k0, int buf) {
#pragma unroll
        for (int it = 0; it < 2; it++) {
            int idx = tid + it * 256;
            int ar = idx >> 2, ac8 = (idx & 3) * 8;
            uint32_t doff = (uint32_t)(buf * ASZ + ar * RSA + ac8) * 2;
            cp16(ah_s + doff, Agh + (size_t)ar * K + k0 + ac8);
            cp16(al_s + doff, Agl + (size_t)ar * K + k0 + ac8);
            int br = idx >> 4, bc8 = (idx & 15) * 8;
            uint32_t boff = (uint32_t)(buf * BSZ + br * RSB + bc8) * 2;
            cp16(bh_s + boff, Bgh + (size_t)(k0 + br) * N + bc8);
            cp16(bl_s + boff, Bgl + (size_t)(k0 + br) * N + bc8);
        }
    };

    load_stage(0, 0);
    CP_COMMIT();

    int buf = 0;
    for (int k0 = 0; k0 < K; k0 += BKK) {
        if (k0 + BKK < K) {
            load_stage(k0 + BKK, buf ^ 1);
            CP_COMMIT();
            CP_WAIT(1);
        } else {
            CP_WAIT(0);
        }
        __syncthreads();

        const uint32_t abo = (uint32_t)(buf * ASZ) * 2;
        const uint32_t bbo = (uint32_t)(buf * BSZ) * 2;
#pragma unroll
        for (int kk = 0; kk < BKK; kk += 16) {
            uint32_t afh[4][4], afl[4][4], bfh[4][2], bfl[4][2];
#pragma unroll
            for (int mt = 0; mt < 4; mt++) {
                uint32_t aoff = abo + (uint32_t)((arow + mt * 16) * RSA + kk + acol) * 2;
                ldsm_x4(afh[mt][0], afh[mt][1], afh[mt][2], afh[mt][3], ah_s + aoff);
                ldsm_x4(afl[mt][0], afl[mt][1], afl[mt][2], afl[mt][3], al_s + aoff);
            }
#pragma unroll
            for (int p = 0; p < 2; p++) {
                uint32_t boff = bbo + (uint32_t)((kk + brow) * RSB + bcolb + p * 16) * 2;
                uint32_t r0, r1, r2, r3;
                ldsm_x4_t(r0, r1, r2, r3, bh_s + boff);
                bfh[2*p][0] = r0; bfh[2*p][1] = r1; bfh[2*p+1][0] = r2; bfh[2*p+1][1] = r3;
                ldsm_x4_t(r0, r1, r2, r3, bl_s + boff);
                bfl[2*p][0] = r0; bfl[2*p][1] = r1; bfl[2*p+1][0] = r2; bfl[2*p+1][1] = r3;
            }
#pragma unroll
            for (int mt = 0; mt < 4; mt++) {
#pragma unroll
                for (int nt = 0; nt < 4; nt++) {
                    mma16816(acc[mt][nt], afh[mt][0], afh[mt][1], afh[mt][2], afh[mt][3],
                             bfh[nt][0], bfh[nt][1]);
                    mma16816(acc[mt][nt], afh[mt][0], afh[mt][1], afh[mt][2], afh[mt][3],
                             bfl[nt][0], bfl[nt][1]);
                    mma16816(acc[mt][nt], afl[mt][0], afl[mt][1], afl[mt][2], afl[mt][3],
                             bfh[nt][0], bfh[nt][1]);
                }
            }
        }
        __syncthreads();
        buf ^= 1;
    }

#pragma unroll
    for (int mt = 0; mt < 4; mt++) {
#pragma unroll
        for (int nt = 0; nt < 4; nt++) {
            int row = m_blk + wm + mt * 16 + (lane >> 2);
            int col = n_blk + wn + nt * 8 + (lane & 3) * 2;
            *(float2*)(C + (size_t)row * N + col) =
                make_float2(acc[mt][nt][0], acc[mt][nt][1]);
            *(float2*)(C + (size_t)(row + 8) * N + col) =
                make_float2(acc[mt][nt][2], acc[mt][nt][3]);
        }
    }
}

// ======= RMSNorm (per head) + RoPE, fp32 in -> bf16 hi/lo out =======
__global__ __launch_bounds__(128) void norm_rope_split_kernel(
    const float* __restrict__ X, const float* __restrict__ scale,
    const int* __restrict__ positions, int rowstride,
    __nv_bfloat16* __restrict__ Oh, __nv_bfloat16* __restrict__ Ol)
{
    const int t = blockIdx.x;
    const int h = blockIdx.y;
    const int d = threadIdx.x;

    const float* p = X + (size_t)t * rowstride + h * HDIM;
    float v = p[d];

    float s = v * v;
#pragma unroll
    for (int off = 16; off > 0; off >>= 1)
        s += __shfl_xor_sync(0xffffffffu, s, off);

    __shared__ float ws[4];
    __shared__ float vals[HDIM];
    if ((d & 31) == 0) ws[d >> 5] = s;
    __syncthreads();
    float tot = ws[0] + ws[1] + ws[2] + ws[3];

    float nv = v * rsqrtf(tot * (1.f / HDIM) + 1e-6f) * scale[d];
    vals[d] = nv;
    __syncthreads();

    float pos = (float)positions[t];
    int j = d & 63;
    float fe = (2.f * (float)j) / (float)HDIM;
    float inv_ts = exp2f(-fe * 13.287712379549449f);
    float ang = pos * inv_ts;
    float sn, cs;
    sincosf(ang, &sn, &cs);

    float out;
    if (d < 64) out = vals[d] * cs - vals[d + 64] * sn;
    else        out = vals[d] * cs + vals[d - 64] * sn;

    __nv_bfloat16 hv = __float2bfloat16_rn(out);
    float res = out - __bfloat162float(hv);
    size_t o = (size_t)t * rowstride + h * HDIM + d;
    Oh[o] = hv;
    Ol[o] = __float2bfloat16_rn(res);
}

// ==================== Tensor-core flash attention (pre-split bf16) ====================
// q-tile 128 (8 warps x 16 rows), key tile 64, double-buffered cp.async K/V.
#define FQT 128
#define FKT 64
#define RSF 136

#define OQH 0
#define OQL 17408
#define OKH 34816           // + buf*8704
#define OKL 52224
#define OVH 69632
#define OVL 87040
#define KVSZ 8704           // 64*136
#define FLASH2_SMEM_ELEMS 104448
#define FLASH2_SMEM_BYTES (FLASH2_SMEM_ELEMS * 2)

__global__ __launch_bounds__(256) void flash_tc2_kernel(
    const __nv_bfloat16* __restrict__ Qh, const __nv_bfloat16* __restrict__ Ql,
    const __nv_bfloat16* __restrict__ Kh, const __nv_bfloat16* __restrict__ Kl,
    const __nv_bfloat16* __restrict__ Vh, const __nv_bfloat16* __restrict__ Vl,
    __nv_bfloat16* __restrict__ Ah, __nv_bfloat16* __restrict__ Al)
{
    extern __shared__ __nv_bfloat16 smf[];
    const int tid  = threadIdx.x;
    const int lane = tid & 31;
    const int warp = tid >> 5;
    const int qb   = blockIdx.x;
    const int h    = blockIdx.y;
    const int t0   = qb * FQT;
    const int kvh  = h >> 2;

    const uint32_t smb  = (uint32_t)__cvta_generic_to_shared(smf);
    const uint32_t qh_s = smb + OQH * 2;
    const uint32_t ql_s = smb + OQL * 2;
    const uint32_t kh_s = smb + OKH * 2;
    const uint32_t kl_s = smb + OKL * 2;
    const uint32_t vh_s = smb + OVH * 2;
    const uint32_t vl_s = smb + OVL * 2;

    int lo = t0 - (WINDOW - 1); if (lo < 0) lo = 0;
    const int tlo = lo >> 6;
    const int thi = (t0 + FQT - 1) >> 6;

    // ---- Q loads (cp.async) ----
#pragma unroll
    for (int it = 0; it < 8; it++) {
        int idx = tid + it * 256;
        int qr = idx >> 4, qc8 = (idx & 15) * 8;
        uint32_t doff = (uint32_t)(qr * RSF + qc8) * 2;
        const size_t goff = (size_t)(t0 + qr) * DMODEL + h * HDIM + qc8;
        cp16(qh_s + doff, Qh + goff);
        cp16(ql_s + doff, Ql + goff);
    }

    auto kv_load = [&](int kt, int buf) {
        const uint32_t bo = (uint32_t)(buf * KVSZ) * 2;
#pragma unroll
        for (int it = 0; it < 4; it++) {
            int idx = tid + it * 256;
            int jr = idx >> 4, jc8 = (idx & 15) * 8;
            uint32_t doff = bo + (uint32_t)(jr * RSF + jc8) * 2;
            const size_t goff = (size_t)(kt * FKT + jr) * KVDIM + kvh * HDIM + jc8;
            cp16(kh_s + doff, Kh + goff);
            cp16(kl_s + doff, Kl + goff);
            cp16(vh_s + doff, Vh + goff);
            cp16(vl_s + doff, Vl + goff);
        }
    };

    kv_load(tlo, 0);
    CP_COMMIT();

    // fragment coordinates
    const int arow   = warp * 16 + (lane & 15);
    const int acol8  = (lane >> 4) * 8;
    const int nb_off = (lane & 7) + ((lane >> 4) << 3);  // B-frag key row (non-trans K)
    const int kb_off = ((lane >> 3) & 1) * 8;            // B-frag k offset
    const int brow   = lane & 15;                        // V-frag (trans)
    const int bcol8  = (lane >> 4) * 8;
    const int r  = lane >> 2;
    const int c2 = (lane & 3) * 2;
    const int row0 = t0 + warp * 16 + r;
    const int row1 = row0 + 8;

    float o[16][4];
#pragma unroll
    for (int nt = 0; nt < 16; nt++)
#pragma unroll
        for (int q = 0; q < 4; q++) o[nt][q] = 0.f;

    float m0 = -1e20f, m1 = -1e20f, l0 = 0.f, l1 = 0.f;
    const float sscale = 0.08838834764831845f;

    int buf = 0;
    for (int kt = tlo; kt <= thi; kt++) {
        if (kt < thi) {
            kv_load(kt + 1, buf ^ 1);
            CP_COMMIT();
            CP_WAIT(1);
        } else {
            CP_WAIT(0);
        }
        __syncthreads();

        const int kbase = kt * FKT;
        const uint32_t kvbo = (uint32_t)(buf * KVSZ) * 2;

        // ---- S = Q K^T (bf16 split, 3 MMAs) ----
        float s[8][4];
#pragma unroll
        for (int nt = 0; nt < 8; nt++)
#pragma unroll
            for (int q = 0; q < 4; q++) s[nt][q] = 0.f;

#pragma unroll
        for (int ks = 0; ks < 8; ks++) {
            uint32_t qah0, qah1, qah2, qah3, qal0, qal1, qal2, qal3;
            uint32_t qoff = (uint32_t)(arow * RSF + ks * 16 + acol8) * 2;
            ldsm_x4(qah0, qah1, qah2, qah3, qh_s + qoff);
            ldsm_x4(qal0, qal1, qal2, qal3, ql_s + qoff);
#pragma unroll
            for (int p = 0; p < 4; p++) {
                uint32_t koff = kvbo +
                    (uint32_t)((p * 16 + nb_off) * RSF + ks * 16 + kb_off) * 2;
                uint32_t kh0, kh1, kh2, kh3, kl0, kl1, kl2, kl3;
                ldsm_x4(kh0, kh1, kh2, kh3, kh_s + koff);
                ldsm_x4(kl0, kl1, kl2, kl3, kl_s + koff);
                mma16816(s[2*p],   qah0, qah1, qah2, qah3, kh0, kh1);
                mma16816(s[2*p],   qah0, qah1, qah2, qah3, kl0, kl1);
                mma16816(s[2*p],   qal0, qal1, qal2, qal3, kh0, kh1);
                mma16816(s[2*p+1], qah0, qah1, qah2, qah3, kh2, kh3);
                mma16816(s[2*p+1], qah0, qah1, qah2, qah3, kl2, kl3);
                mma16816(s[2*p+1], qal0, qal1, qal2, qal3, kh2, kh3);
            }
        }

        // ---- mask + scale + online softmax ----
        float rm0 = -1e30f, rm1 = -1e30f;
#pragma unroll
        for (int nt = 0; nt < 8; nt++) {
            int kj = kbase + nt * 8 + c2;
#pragma unroll
            for (int e = 0; e < 2; e++) {
                int kc = kj + e;
                bool v0 = (kc <= row0) && (kc >= row0 - (WINDOW - 1));
                bool v1 = (kc <= row1) && (kc >= row1 - (WINDOW - 1));
                s[nt][e]     = v0 ? s[nt][e]     * sscale : -1e30f;
                s[nt][2 + e] = v1 ? s[nt][2 + e] * sscale : -1e30f;
                rm0 = fmaxf(rm0, s[nt][e]);
                rm1 = fmaxf(rm1, s[nt][2 + e]);
            }
        }
        rm0 = fmaxf(rm0, __shfl_xor_sync(0xffffffffu, rm0, 1));
        rm0 = fmaxf(rm0, __shfl_xor_sync(0xffffffffu, rm0, 2));
        rm1 = fmaxf(rm1, __shfl_xor_sync(0xffffffffu, rm1, 1));
        rm1 = fmaxf(rm1, __shfl_xor_sync(0xffffffffu, rm1, 2));

        float mn0 = fmaxf(m0, rm0);
        float mn1 = fmaxf(m1, rm1);
        float cf0 = __expf(m0 - mn0);
        float cf1 = __expf(m1 - mn1);
        float sum0 = 0.f, sum1 = 0.f;
#pragma unroll
        for (int nt = 0; nt < 8; nt++) {
            s[nt][0] = __expf(s[nt][0] - mn0);
            s[nt][1] = __expf(s[nt][1] - mn0);
            s[nt][2] = __expf(s[nt][2] - mn1);
            s[nt][3] = __expf(s[nt][3] - mn1);
            sum0 += s[nt][0] + s[nt][1];
            sum1 += s[nt][2] + s[nt][3];
        }
        sum0 += __shfl_xor_sync(0xffffffffu, sum0, 1);
        sum0 += __shfl_xor_sync(0xffffffffu, sum0, 2);
        sum1 += __shfl_xor_sync(0xffffffffu, sum1, 1);
        sum1 += __shfl_xor_sync(0xffffffffu, sum1, 2);

        m0 = mn0; m1 = mn1;
        l0 = l0 * cf0 + sum0;
        l1 = l1 * cf1 + sum1;
#pragma unroll
        for (int nt = 0; nt < 16; nt++) {
            o[nt][0] *= cf0; o[nt][1] *= cf0;
            o[nt][2] *= cf1; o[nt][3] *= cf1;
        }

        // ---- build P fragments (hi/lo) ----
        uint32_t pfh[4][4], pfl[4][4];
#pragma unroll
        for (int kk = 0; kk < 4; kk++) {
            int ta = 2 * kk, tb = 2 * kk + 1;
            float la, lb;
            pfh[kk][0] = pack_hi2(s[ta][0], s[ta][1], la, lb); pfl[kk][0] = pack2(la, lb);
            pfh[kk][1] = pack_hi2(s[ta][2], s[ta][3], la, lb); pfl[kk][1] = pack2(la, lb);
            pfh[kk][2] = pack_hi2(s[tb][0], s[tb][1], la, lb); pfl[kk][2] = pack2(la, lb);
            pfh[kk][3] = pack_hi2(s[tb][2], s[tb][3], la, lb); pfl[kk][3] = pack2(la, lb);
        }

        // ---- O += P V (bf16 split, 3 MMAs) ----
#pragma unroll
        for (int kk = 0; kk < 4; kk++) {
#pragma unroll
            for (int p = 0; p < 8; p++) {
                uint32_t boff = kvbo +
                    (uint32_t)((kk * 16 + brow) * RSF + p * 16 + bcol8) * 2;
                uint32_t vh0, vh1, vh2, vh3, vl0, vl1, vl2, vl3;
                ldsm_x4_t(vh0, vh1, vh2, vh3, vh_s + boff);
                ldsm_x4_t(vl0, vl1, vl2, vl3, vl_s + boff);
                mma16816(o[2*p],   pfh[kk][0], pfh[kk][1], pfh[kk][2], pfh[kk][3], vh0, vh1);
                mma16816(o[2*p],   pfl[kk][0], pfl[kk][1], pfl[kk][2], pfl[kk][3], vh0, vh1);
                mma16816(o[2*p],   pfh[kk][0], pfh[kk][1], pfh[kk][2], pfh[kk][3], vl0, vl1);
                mma16816(o[2*p+1], pfh[kk][0], pfh[kk][1], pfh[kk][2], pfh[kk][3], vh2, vh3);
                mma16816(o[2*p+1], pfl[kk][0], pfl[kk][1], pfl[kk][2], pfl[kk][3], vh2, vh3);
                mma16816(o[2*p+1], pfh[kk][0], pfh[kk][1], pfh[kk][2], pfh[kk][3], vl2, vl3);
            }
        }
        __syncthreads();
        buf ^= 1;
    }

    // ---- epilogue: divide by l, split-write attn (bf16 hi/lo) ----
    float inv0 = 1.f / l0;
    float inv1 = 1.f / l1;
#pragma unroll
    for (int nt = 0; nt < 16; nt++) {
        int col = nt * 8 + c2;
        size_t o0 = (size_t)row0 * DMODEL + h * HDIM + col;
        size_t o1 = (size_t)row1 * DMODEL + h * HDIM + col;
        float a0 = o[nt][0] * inv0, a1 = o[nt][1] * inv0;
        float b0 = o[nt][2] * inv1, b1 = o[nt][3] * inv1;
        float r0a, r1a, r0b, r1b;
        uint32_t h0 = pack_hi2(a0, a1, r0a, r1a);
        uint32_t h1 = pack_hi2(b0, b1, r0b, r1b);
        *(uint32_t*)(Ah + o0) = h0;
        *(uint32_t*)(Al + o0) = pack2(r0a, r1a);
        *(uint32_t*)(Ah + o1) = h1;
        *(uint32_t*)(Al + o1) = pack2(r0b, r1b);
    }
}

// ================================ launch ================================
extern "C" void kernel_launch(void* const* d_in, const int* in_sizes, int n_in,
                              void* d_out, int out_size)
{
    const float* x         = (const float*)d_in[0];
    const int*   positions = (const int*)  d_in[1];
    const float* Wq        = (const float*)d_in[2];
    const float* Wk        = (const float*)d_in[3];
    const float* Wv        = (const float*)d_in[4];
    const float* Wo        = (const float*)d_in[5];
    const float* q_scale   = (const float*)d_in[6];
    const float* k_scale   = (const float*)d_in[7];
    float* out = (float*)d_out;

    float *q_ptr, *k_ptr, *v_ptr;
    cudaGetSymbolAddress((void**)&q_ptr, g_q);
    cudaGetSymbolAddress((void**)&k_ptr, g_k);
    cudaGetSymbolAddress((void**)&v_ptr, g_v);

    __nv_bfloat16 *xh, *xl, *wqh, *wql, *wkh, *wkl, *wvh, *wvl, *woh, *wol;
    __nv_bfloat16 *qh, *ql, *kh, *kl, *vh, *vl, *ah, *al;
    cudaGetSymbolAddress((void**)&xh,  g_xh);  cudaGetSymbolAddress((void**)&xl,  g_xl);
    cudaGetSymbolAddress((void**)&wqh, g_wqh); cudaGetSymbolAddress((void**)&wql, g_wql);
    cudaGetSymbolAddress((void**)&wkh, g_wkh); cudaGetSymbolAddress((void**)&wkl, g_wkl);
    cudaGetSymbolAddress((void**)&wvh, g_wvh); cudaGetSymbolAddress((void**)&wvl, g_wvl);
    cudaGetSymbolAddress((void**)&woh, g_woh); cudaGetSymbolAddress((void**)&wol, g_wol);
    cudaGetSymbolAddress((void**)&qh,  g_qh);  cudaGetSymbolAddress((void**)&ql,  g_ql);
    cudaGetSymbolAddress((void**)&kh,  g_kh);  cudaGetSymbolAddress((void**)&kl,  g_kl);
    cudaGetSymbolAddress((void**)&vh,  g_vh);  cudaGetSymbolAddress((void**)&vl,  g_vl);
    cudaGetSymbolAddress((void**)&ah,  g_ah);  cudaGetSymbolAddress((void**)&al,  g_al);

    cudaFuncSetAttribute(gemm_tc2_kernel,
                         cudaFuncAttributeMaxDynamicSharedMemorySize, GEMM_SMEM_BYTES);
    cudaFuncSetAttribute(flash_tc2_kernel,
                         cudaFuncAttributeMaxDynamicSharedMemorySize, FLASH2_SMEM_BYTES);

    // ---- pre-split all GEMM operands into bf16 hi/lo ----
    {
        int n4;
        n4 = L_SEQ * DMODEL / 4;
        split_kernel<<<(n4 + 255) / 256, 256>>>((const float4*)x, (uint2*)xh, (uint2*)xl, n4);
        n4 = DMODEL * DMODEL / 4;
        split_kernel<<<(n4 + 255) / 256, 256>>>((const float4*)Wq, (uint2*)wqh, (uint2*)wql, n4);
        split_kernel<<<(n4 + 255) / 256, 256>>>((const float4*)Wo, (uint2*)woh, (uint2*)wol, n4);
        n4 = DMODEL * KVDIM / 4;
        split_kernel<<<(n4 + 255) / 256, 256>>>((const float4*)Wk, (uint2*)wkh, (uint2*)wkl, n4);
        split_kernel<<<(n4 + 255) / 256, 256>>>((const float4*)Wv, (uint2*)wvh, (uint2*)wvl, n4);
    }

    dim3 blk(256);
    // QKV projections
    gemm_tc2_kernel<<<dim3(DMODEL / BN, L_SEQ / BM), blk, GEMM_SMEM_BYTES>>>(
        L_SEQ, DMODEL, DMODEL, xh, xl, wqh, wql, q_ptr);
    gemm_tc2_kernel<<<dim3(KVDIM / BN, L_SEQ / BM), blk, GEMM_SMEM_BYTES>>>(
        L_SEQ, KVDIM, DMODEL, xh, xl, wkh, wkl, k_ptr);
    gemm_tc2_kernel<<<dim3(KVDIM / BN, L_SEQ / BM), blk, GEMM_SMEM_BYTES>>>(
        L_SEQ, KVDIM, DMODEL, xh, xl, wvh, wvl, v_ptr);

    // norm+rope: q,k -> bf16 hi/lo; v -> split
    norm_rope_split_kernel<<<dim3(L_SEQ, NH),  128>>>(q_ptr, q_scale, positions, DMODEL, qh, ql);
    norm_rope_split_kernel<<<dim3(L_SEQ, NKV), 128>>>(k_ptr, k_scale, positions, KVDIM, kh, kl);
    {
        int n4 = L_SEQ * KVDIM / 4;
        split_kernel<<<(n4 + 255) / 256, 256>>>((const float4*)v_ptr, (uint2*)vh, (uint2*)vl, n4);
    }

    // sliding-window flash attention (pre-split bf16, double-buffered)
    flash_tc2_kernel<<<dim3(L_SEQ / FQT, NH), 256, FLASH2_SMEM_BYTES>>>(
        qh, ql, kh, kl, vh, vl, ah, al);

    // output projection
    gemm_tc2_kernel<<<dim3(DMODEL / BN, L_SEQ / BM), blk, GEMM_SMEM_BYTES>>>(
        L_SEQ, DMODEL, DMODEL, ah, al, woh, wol, out);
}